// round 16
// baseline (speedup 1.0000x reference)
#include <cuda_runtime.h>
#include <cuda_fp16.h>

#define N_NODES  100000
#define N_EDGES  3200000
#define N_GRAPHS 128
#define NB_SCAN  ((N_NODES + 255) / 256)   // 391

// ---------------- scratch (device globals) -----------------------------------
__device__ int   g_cnt[N_NODES];               // in-degree (zeroed by k_l3 after use)
__device__ int   g_off[N_NODES];               // CSR base per dst (block-atomic bases)
__device__ int   g_cur[N_NODES];               // scatter cursors
__device__ int   g_total;                      // scan allocator (reset by k_final)
__device__ float g_dinv[N_NODES];
__device__ __align__(16) float g_y[N_NODES * 4];     // (dinv*x0, dinv*x1, dinv*x2, dinv)
__device__ int   g_srcs[N_EDGES];                    // src ids grouped by dst
__device__ __align__(64) __half g_h1[N_NODES * 32];  // fp16: dinv * relu(t1@W1+b1)
__device__ __align__(8)  float  g_p [N_NODES * 2];   // dinv * ((relu(t2@W2+b2))@W3)
__device__ __align__(8)  float  g_t3[N_NODES * 2];
__device__ float g_gsum[N_GRAPHS * 2];               // zeroed by k_final after use
__device__ float g_gcnt[N_GRAPHS];

// ---------------- kernels ----------------------------------------------------

// histogram of dst, 4 edges/thread (int4 loads)
__global__ void k_hist(const int* __restrict__ ei) {
    int e = (blockIdx.x * blockDim.x + threadIdx.x) << 2;
    if (e >= N_EDGES) return;
    const int4 d4 = *reinterpret_cast<const int4*>(&ei[N_EDGES + e]);
    atomicAdd(&g_cnt[d4.x], 1);
    atomicAdd(&g_cnt[d4.y], 1);
    atomicAdd(&g_cnt[d4.z], 1);
    atomicAdd(&g_cnt[d4.w], 1);
}

// single-pass scan: block-local scan + atomic block base; fused dinv/y build
__global__ void k_scan(const float* __restrict__ x) {
    __shared__ int sh[256];
    __shared__ int sbase;
    int tid = threadIdx.x;
    int i = blockIdx.x * 256 + tid;
    int v = (i < N_NODES) ? g_cnt[i] : 0;
    sh[tid] = v;
    __syncthreads();
    for (int ofs = 1; ofs < 256; ofs <<= 1) {
        int t = (tid >= ofs) ? sh[tid - ofs] : 0;
        __syncthreads();
        sh[tid] += t;
        __syncthreads();
    }
    if (tid == 255) sbase = atomicAdd(&g_total, sh[255]);
    __syncthreads();
    if (i < N_NODES) {
        int off = sbase + sh[tid] - v;   // exclusive within block + block base
        g_off[i] = off;
        g_cur[i] = off;
        float dv = rsqrtf((float)v + 1.0f);   // +1 = self-loop
        g_dinv[i] = dv;
        *reinterpret_cast<float4*>(&g_y[4 * i]) =
            make_float4(dv * x[3 * i], dv * x[3 * i + 1], dv * x[3 * i + 2], dv);
    }
}

// scatter edges into dst-CSR (src only — 4B payload), 4 edges/thread
__global__ void k_scatter(const int* __restrict__ ei) {
    int e = (blockIdx.x * blockDim.x + threadIdx.x) << 2;
    if (e >= N_EDGES) return;
    const int4 s4 = *reinterpret_cast<const int4*>(&ei[e]);
    const int4 d4 = *reinterpret_cast<const int4*>(&ei[N_EDGES + e]);
    g_srcs[atomicAdd(&g_cur[d4.x], 1)] = s4.x;
    g_srcs[atomicAdd(&g_cur[d4.y], 1)] = s4.y;
    g_srcs[atomicAdd(&g_cur[d4.z], 1)] = s4.z;
    g_srcs[atomicAdd(&g_cur[d4.w], 1)] = s4.w;
}

// L1 aggregation + 3->32 GEMV + ReLU, warp per dst node; writes h1' = fp16(dinv*relu)
__global__ void k_l1node1(const float* __restrict__ W1, const float* __restrict__ b1) {
    int gid = blockIdx.x * blockDim.x + threadIdx.x;
    int n = gid >> 5;
    int lane = gid & 31;
    if (n >= N_NODES) return;
    int o0 = g_off[n];
    int o1 = o0 + g_cnt[n];
    float ax = 0.0f, ay = 0.0f, az = 0.0f;
    for (int i = o0 + lane; i < o1; i += 32) {
        const float4 ys = *reinterpret_cast<const float4*>(&g_y[4 * g_srcs[i]]);
        ax += ys.x; ay += ys.y; az += ys.z;
    }
#pragma unroll
    for (int m = 16; m > 0; m >>= 1) {
        ax += __shfl_xor_sync(0xffffffffu, ax, m);
        ay += __shfl_xor_sync(0xffffffffu, ay, m);
        az += __shfl_xor_sync(0xffffffffu, az, m);
    }
    const float4 yn = *reinterpret_cast<const float4*>(&g_y[4 * n]);
    float dd = yn.w;
    float t1x = dd * (ax + yn.x);
    float t1y = dd * (ay + yn.y);
    float t1z = dd * (az + yn.z);
    float acc = b1[lane];
    acc = fmaf(t1x, W1[lane], acc);
    acc = fmaf(t1y, W1[32 + lane], acc);
    acc = fmaf(t1z, W1[64 + lane], acc);
    g_h1[(n << 5) + lane] = __float2half(dd * fmaxf(acc, 0.0f));   // pre-scaled h1'
}

// L2 aggregation (coalesced src list + shfl-distribute, 64B fp16 row pulls)
// + fused 32->64 ReLU + 64->2 GEMV; writes p' = dinv*p
__global__ void k_l2node23(const float* __restrict__ W2, const float* __restrict__ b2,
                           const float* __restrict__ W3) {
    __shared__ float sW2[32 * 64];
    __shared__ float sW3[64 * 2];
    __shared__ float sb2[64];
    int tid = threadIdx.x;
    for (int i = tid; i < 32 * 64; i += blockDim.x) sW2[i] = W2[i];
    if (tid < 128) sW3[tid] = W3[tid];
    if (tid < 64)  sb2[tid] = b2[tid];
    __syncthreads();

    int lane = tid & 31;
    int gw = (blockIdx.x * blockDim.x + tid) >> 5;
    int nwarps = (gridDim.x * blockDim.x) >> 5;

    for (int n = gw; n < N_NODES; n += nwarps) {
        float dd = g_dinv[n];
        int o0 = g_off[n];
        int o1 = o0 + g_cnt[n];
        float acc = __half2float(g_h1[(n << 5) + lane]);   // self term (pre-scaled)
        int i = o0;
        for (; i + 32 <= o1; i += 32) {
            int s = g_srcs[i + lane];                // one coalesced 128B load
#pragma unroll
            for (int j = 0; j < 32; j++) {
                int sj = __shfl_sync(0xffffffffu, s, j);
                acc += __half2float(g_h1[(sj << 5) + lane]);  // 64B row pulls
            }
        }
        int rem = o1 - i;
        if (rem > 0) {
            int s = (lane < rem) ? g_srcs[i + lane] : 0;
            for (int j = 0; j < rem; j++) {
                int sj = __shfl_sync(0xffffffffu, s, j);
                acc += __half2float(g_h1[(sj << 5) + lane]);
            }
        }
        float t2 = dd * acc;
        // GEMV 32->64 + ReLU + 64->2
        float a0 = sb2[lane];
        float a1 = sb2[lane + 32];
#pragma unroll
        for (int k = 0; k < 32; k++) {
            float tk = __shfl_sync(0xffffffffu, t2, k);
            a0 = fmaf(tk, sW2[k * 64 + lane], a0);
            a1 = fmaf(tk, sW2[k * 64 + lane + 32], a1);
        }
        a0 = fmaxf(a0, 0.0f);
        a1 = fmaxf(a1, 0.0f);
        float c0 = a0 * sW3[2 * lane]     + a1 * sW3[2 * lane + 64];
        float c1 = a0 * sW3[2 * lane + 1] + a1 * sW3[2 * lane + 65];
#pragma unroll
        for (int m = 16; m > 0; m >>= 1) {
            c0 += __shfl_xor_sync(0xffffffffu, c0, m);
            c1 += __shfl_xor_sync(0xffffffffu, c1, m);
        }
        if (lane == 0)
            *reinterpret_cast<float2*>(&g_p[2 * n]) = make_float2(dd * c0, dd * c1);
    }
}

// L3 aggregation at width 2, warp per dst node; zeroes g_cnt for next replay
__global__ void k_l3() {
    int gid = blockIdx.x * blockDim.x + threadIdx.x;
    int n = gid >> 5;
    int lane = gid & 31;
    if (n >= N_NODES) return;
    int o0 = g_off[n];
    int o1 = o0 + g_cnt[n];
    float a0 = 0.0f, a1 = 0.0f;
    for (int i = o0 + lane; i < o1; i += 32) {
        const float2 ps = *reinterpret_cast<const float2*>(&g_p[2 * g_srcs[i]]);
        a0 += ps.x;
        a1 += ps.y;
    }
#pragma unroll
    for (int m = 16; m > 0; m >>= 1) {
        a0 += __shfl_xor_sync(0xffffffffu, a0, m);
        a1 += __shfl_xor_sync(0xffffffffu, a1, m);
    }
    if (lane == 0) {
        float dd = g_dinv[n];
        const float2 pn = *reinterpret_cast<const float2*>(&g_p[2 * n]);
        *reinterpret_cast<float2*>(&g_t3[2 * n]) =
            make_float2(dd * (a0 + pn.x), dd * (a1 + pn.y));
        g_cnt[n] = 0;                                // ready for next replay
    }
}

// mean-pool: shared pre-reduction per block
__global__ void k_pool(const int* __restrict__ batch) {
    __shared__ float ss[N_GRAPHS * 2];
    __shared__ float sc[N_GRAPHS];
    int tid = threadIdx.x;
    for (int i = tid; i < N_GRAPHS * 2; i += blockDim.x) ss[i] = 0.0f;
    for (int i = tid; i < N_GRAPHS; i += blockDim.x)     sc[i] = 0.0f;
    __syncthreads();
    int n = blockIdx.x * blockDim.x + tid;
    if (n < N_NODES) {
        int g = batch[n];
        atomicAdd(&ss[2 * g + 0], g_t3[2 * n + 0]);
        atomicAdd(&ss[2 * g + 1], g_t3[2 * n + 1]);
        atomicAdd(&sc[g], 1.0f);
    }
    __syncthreads();
    if (tid < N_GRAPHS * 2) atomicAdd(&g_gsum[tid], ss[tid]);
    if (tid < N_GRAPHS)     atomicAdd(&g_gcnt[tid], sc[tid]);
}

// finalize + reset accumulators for next replay
__global__ void k_final(const float* __restrict__ b3, float* __restrict__ out) {
    int i = threadIdx.x;
    float r = 0.0f;
    if (i < N_GRAPHS * 2) {
        int g = i >> 1, j = i & 1;
        r = g_gsum[i] / fmaxf(g_gcnt[g], 1.0f) + b3[j];
    }
    __syncthreads();
    if (i < N_GRAPHS * 2) {
        out[i] = r;
        g_gsum[i] = 0.0f;
    }
    if (i < N_GRAPHS) g_gcnt[i] = 0.0f;
    if (i == 0)       g_total = 0;
}

// ---------------- launch ------------------------------------------------------
extern "C" void kernel_launch(void* const* d_in, const int* in_sizes, int n_in,
                              void* d_out, int out_size) {
    const float* x     = (const float*)d_in[0];
    const int*   ei    = (const int*)d_in[1];    // int32 (JAX x64 disabled)
    const int*   batch = (const int*)d_in[2];
    const float* W1    = (const float*)d_in[3];
    const float* b1    = (const float*)d_in[4];
    const float* W2    = (const float*)d_in[5];
    const float* b2    = (const float*)d_in[6];
    const float* W3    = (const float*)d_in[7];
    const float* b3    = (const float*)d_in[8];
    float* out = (float*)d_out;

    const int TB = 256;
    const int nb_nodes = (N_NODES + TB - 1) / TB;        // 391
    const int nb_e4    = (N_EDGES / 4 + TB - 1) / TB;    // 3125
    const int nb_nwarp = (N_NODES * 32 + TB - 1) / TB;   // 12500

    k_hist<<<nb_e4, TB>>>(ei);
    k_scan<<<NB_SCAN, TB>>>(x);
    k_scatter<<<nb_e4, TB>>>(ei);
    k_l1node1<<<nb_nwarp, TB>>>(W1, b1);
    k_l2node23<<<1184, TB>>>(W2, b2, W3);   // 8 blocks/SM, grid-stride
    k_l3<<<nb_nwarp, TB>>>();
    k_pool<<<nb_nodes, TB>>>(batch);
    k_final<<<1, 256>>>(b3, out);
}

// round 17
// speedup vs baseline: 1.0567x; 1.0567x over previous
#include <cuda_runtime.h>
#include <cuda_fp16.h>

#define N_NODES  100000
#define N_EDGES  3200000
#define N_GRAPHS 128
#define NB_SCAN  ((N_NODES + 255) / 256)   // 391

// ---------------- scratch (device globals) -----------------------------------
__device__ int   g_cnt[N_NODES];               // in-degree (zeroed by k_l3 after use)
__device__ int   g_off[N_NODES];               // CSR base per dst (block-atomic bases)
__device__ int   g_cur[N_NODES];               // scatter cursors
__device__ int   g_total;                      // scan allocator (reset by k_final)
__device__ float g_dinv[N_NODES];
__device__ __align__(16) float g_y[N_NODES * 4];     // (dinv*x0, dinv*x1, dinv*x2, dinv)
__device__ int   g_srcs[N_EDGES];                    // src ids grouped by dst
__device__ __align__(64) __half g_h1[N_NODES * 32];  // fp16: dinv * relu(t1@W1+b1)
__device__ __align__(8)  float  g_p [N_NODES * 2];   // dinv * ((relu(t2@W2+b2))@W3)
__device__ __align__(8)  float  g_t3[N_NODES * 2];
__device__ float g_gsum[N_GRAPHS * 2];               // zeroed by k_final after use
__device__ float g_gcnt[N_GRAPHS];

// ---------------- kernels ----------------------------------------------------

// histogram of dst, 4 edges/thread (int4 loads)
__global__ void k_hist(const int* __restrict__ ei) {
    int e = (blockIdx.x * blockDim.x + threadIdx.x) << 2;
    if (e >= N_EDGES) return;
    const int4 d4 = *reinterpret_cast<const int4*>(&ei[N_EDGES + e]);
    atomicAdd(&g_cnt[d4.x], 1);
    atomicAdd(&g_cnt[d4.y], 1);
    atomicAdd(&g_cnt[d4.z], 1);
    atomicAdd(&g_cnt[d4.w], 1);
}

// single-pass scan: block-local scan + atomic block base; fused dinv/y build
__global__ void k_scan(const float* __restrict__ x) {
    __shared__ int sh[256];
    __shared__ int sbase;
    int tid = threadIdx.x;
    int i = blockIdx.x * 256 + tid;
    int v = (i < N_NODES) ? g_cnt[i] : 0;
    sh[tid] = v;
    __syncthreads();
    for (int ofs = 1; ofs < 256; ofs <<= 1) {
        int t = (tid >= ofs) ? sh[tid - ofs] : 0;
        __syncthreads();
        sh[tid] += t;
        __syncthreads();
    }
    if (tid == 255) sbase = atomicAdd(&g_total, sh[255]);
    __syncthreads();
    if (i < N_NODES) {
        int off = sbase + sh[tid] - v;   // exclusive within block + block base
        g_off[i] = off;
        g_cur[i] = off;
        float dv = rsqrtf((float)v + 1.0f);   // +1 = self-loop
        g_dinv[i] = dv;
        *reinterpret_cast<float4*>(&g_y[4 * i]) =
            make_float4(dv * x[3 * i], dv * x[3 * i + 1], dv * x[3 * i + 2], dv);
    }
}

// scatter edges into dst-CSR (src only — 4B payload), 4 edges/thread
__global__ void k_scatter(const int* __restrict__ ei) {
    int e = (blockIdx.x * blockDim.x + threadIdx.x) << 2;
    if (e >= N_EDGES) return;
    const int4 s4 = *reinterpret_cast<const int4*>(&ei[e]);
    const int4 d4 = *reinterpret_cast<const int4*>(&ei[N_EDGES + e]);
    g_srcs[atomicAdd(&g_cur[d4.x], 1)] = s4.x;
    g_srcs[atomicAdd(&g_cur[d4.y], 1)] = s4.y;
    g_srcs[atomicAdd(&g_cur[d4.z], 1)] = s4.z;
    g_srcs[atomicAdd(&g_cur[d4.w], 1)] = s4.w;
}

// L1 aggregation + 3->32 GEMV + ReLU. 8 lanes per node, 4 nodes per warp:
// MLP~4 per lane, 3-round reduction, packed 8B fp16 stores.
__global__ void k_l1node1(const float* __restrict__ W1, const float* __restrict__ b1) {
    int gid = blockIdx.x * blockDim.x + threadIdx.x;
    int lane = gid & 31;
    int n = ((gid >> 5) << 2) + (lane >> 3);   // warp covers nodes 4w..4w+3
    int sl = lane & 7;
    if (n >= N_NODES) return;
    int o0 = g_off[n];
    int o1 = o0 + g_cnt[n];
    float ax = 0.0f, ay = 0.0f, az = 0.0f;
    for (int i = o0 + sl; i < o1; i += 8) {
        const float4 ys = *reinterpret_cast<const float4*>(&g_y[g_srcs[i] << 2]);
        ax += ys.x; ay += ys.y; az += ys.z;
    }
#pragma unroll
    for (int m = 4; m > 0; m >>= 1) {
        ax += __shfl_xor_sync(0xffffffffu, ax, m);
        ay += __shfl_xor_sync(0xffffffffu, ay, m);
        az += __shfl_xor_sync(0xffffffffu, az, m);
    }
    const float4 yn = *reinterpret_cast<const float4*>(&g_y[n << 2]);
    float dd = yn.w;
    float t1x = dd * (ax + yn.x);
    float t1y = dd * (ay + yn.y);
    float t1z = dd * (az + yn.z);
    int f = sl << 2;                            // lane owns channels f..f+3
    float h[4];
#pragma unroll
    for (int j = 0; j < 4; j++) {
        float acc = b1[f + j];
        acc = fmaf(t1x, W1[f + j], acc);
        acc = fmaf(t1y, W1[32 + f + j], acc);
        acc = fmaf(t1z, W1[64 + f + j], acc);
        h[j] = dd * fmaxf(acc, 0.0f);           // pre-scaled h1'
    }
    union { uint2 u; __half2 h2[2]; } pk;
    pk.h2[0] = __floats2half2_rn(h[0], h[1]);
    pk.h2[1] = __floats2half2_rn(h[2], h[3]);
    *reinterpret_cast<uint2*>(&g_h1[(n << 5) + f]) = pk.u;
}

// L2 aggregation (coalesced src list + shfl-distribute, 64B fp16 row pulls)
// + fused 32->64 ReLU + 64->2 GEMV; writes p' = dinv*p
__global__ void k_l2node23(const float* __restrict__ W2, const float* __restrict__ b2,
                           const float* __restrict__ W3) {
    __shared__ float sW2[32 * 64];
    __shared__ float sW3[64 * 2];
    __shared__ float sb2[64];
    int tid = threadIdx.x;
    for (int i = tid; i < 32 * 64; i += blockDim.x) sW2[i] = W2[i];
    if (tid < 128) sW3[tid] = W3[tid];
    if (tid < 64)  sb2[tid] = b2[tid];
    __syncthreads();

    int lane = tid & 31;
    int gw = (blockIdx.x * blockDim.x + tid) >> 5;
    int nwarps = (gridDim.x * blockDim.x) >> 5;

    for (int n = gw; n < N_NODES; n += nwarps) {
        float dd = g_dinv[n];
        int o0 = g_off[n];
        int o1 = o0 + g_cnt[n];
        float acc = __half2float(g_h1[(n << 5) + lane]);   // self term (pre-scaled)
        int i = o0;
        for (; i + 32 <= o1; i += 32) {
            int s = g_srcs[i + lane];                // one coalesced 128B load
#pragma unroll
            for (int j = 0; j < 32; j++) {
                int sj = __shfl_sync(0xffffffffu, s, j);
                acc += __half2float(g_h1[(sj << 5) + lane]);  // 64B row pulls
            }
        }
        int rem = o1 - i;
        if (rem > 0) {
            int s = (lane < rem) ? g_srcs[i + lane] : 0;
            for (int j = 0; j < rem; j++) {
                int sj = __shfl_sync(0xffffffffu, s, j);
                acc += __half2float(g_h1[(sj << 5) + lane]);
            }
        }
        float t2 = dd * acc;
        // GEMV 32->64 + ReLU + 64->2
        float a0 = sb2[lane];
        float a1 = sb2[lane + 32];
#pragma unroll
        for (int k = 0; k < 32; k++) {
            float tk = __shfl_sync(0xffffffffu, t2, k);
            a0 = fmaf(tk, sW2[k * 64 + lane], a0);
            a1 = fmaf(tk, sW2[k * 64 + lane + 32], a1);
        }
        a0 = fmaxf(a0, 0.0f);
        a1 = fmaxf(a1, 0.0f);
        float c0 = a0 * sW3[2 * lane]     + a1 * sW3[2 * lane + 64];
        float c1 = a0 * sW3[2 * lane + 1] + a1 * sW3[2 * lane + 65];
#pragma unroll
        for (int m = 16; m > 0; m >>= 1) {
            c0 += __shfl_xor_sync(0xffffffffu, c0, m);
            c1 += __shfl_xor_sync(0xffffffffu, c1, m);
        }
        if (lane == 0)
            *reinterpret_cast<float2*>(&g_p[2 * n]) = make_float2(dd * c0, dd * c1);
    }
}

// L3 aggregation at width 2. 8 lanes per node, 4 nodes per warp; zeroes g_cnt.
__global__ void k_l3() {
    int gid = blockIdx.x * blockDim.x + threadIdx.x;
    int lane = gid & 31;
    int n = ((gid >> 5) << 2) + (lane >> 3);
    int sl = lane & 7;
    if (n >= N_NODES) return;
    int o0 = g_off[n];
    int o1 = o0 + g_cnt[n];
    float a0 = 0.0f, a1 = 0.0f;
    for (int i = o0 + sl; i < o1; i += 8) {
        const float2 ps = *reinterpret_cast<const float2*>(&g_p[2 * g_srcs[i]]);
        a0 += ps.x;
        a1 += ps.y;
    }
#pragma unroll
    for (int m = 4; m > 0; m >>= 1) {
        a0 += __shfl_xor_sync(0xffffffffu, a0, m);
        a1 += __shfl_xor_sync(0xffffffffu, a1, m);
    }
    if (sl == 0) {
        float dd = g_dinv[n];
        const float2 pn = *reinterpret_cast<const float2*>(&g_p[2 * n]);
        *reinterpret_cast<float2*>(&g_t3[2 * n]) =
            make_float2(dd * (a0 + pn.x), dd * (a1 + pn.y));
        g_cnt[n] = 0;                                // ready for next replay
    }
}

// mean-pool: shared pre-reduction per block
__global__ void k_pool(const int* __restrict__ batch) {
    __shared__ float ss[N_GRAPHS * 2];
    __shared__ float sc[N_GRAPHS];
    int tid = threadIdx.x;
    for (int i = tid; i < N_GRAPHS * 2; i += blockDim.x) ss[i] = 0.0f;
    for (int i = tid; i < N_GRAPHS; i += blockDim.x)     sc[i] = 0.0f;
    __syncthreads();
    int n = blockIdx.x * blockDim.x + tid;
    if (n < N_NODES) {
        int g = batch[n];
        atomicAdd(&ss[2 * g + 0], g_t3[2 * n + 0]);
        atomicAdd(&ss[2 * g + 1], g_t3[2 * n + 1]);
        atomicAdd(&sc[g], 1.0f);
    }
    __syncthreads();
    if (tid < N_GRAPHS * 2) atomicAdd(&g_gsum[tid], ss[tid]);
    if (tid < N_GRAPHS)     atomicAdd(&g_gcnt[tid], sc[tid]);
}

// finalize + reset accumulators for next replay
__global__ void k_final(const float* __restrict__ b3, float* __restrict__ out) {
    int i = threadIdx.x;
    float r = 0.0f;
    if (i < N_GRAPHS * 2) {
        int g = i >> 1, j = i & 1;
        r = g_gsum[i] / fmaxf(g_gcnt[g], 1.0f) + b3[j];
    }
    __syncthreads();
    if (i < N_GRAPHS * 2) {
        out[i] = r;
        g_gsum[i] = 0.0f;
    }
    if (i < N_GRAPHS) g_gcnt[i] = 0.0f;
    if (i == 0)       g_total = 0;
}

// ---------------- launch ------------------------------------------------------
extern "C" void kernel_launch(void* const* d_in, const int* in_sizes, int n_in,
                              void* d_out, int out_size) {
    const float* x     = (const float*)d_in[0];
    const int*   ei    = (const int*)d_in[1];    // int32 (JAX x64 disabled)
    const int*   batch = (const int*)d_in[2];
    const float* W1    = (const float*)d_in[3];
    const float* b1    = (const float*)d_in[4];
    const float* W2    = (const float*)d_in[5];
    const float* b2    = (const float*)d_in[6];
    const float* W3    = (const float*)d_in[7];
    const float* b3    = (const float*)d_in[8];
    float* out = (float*)d_out;

    const int TB = 256;
    const int nb_nodes = (N_NODES + TB - 1) / TB;        // 391
    const int nb_e4    = (N_EDGES / 4 + TB - 1) / TB;    // 3125
    const int nb_n8    = (N_NODES * 8 + TB - 1) / TB;    // 3125 (8 lanes/node)

    k_hist<<<nb_e4, TB>>>(ei);
    k_scan<<<NB_SCAN, TB>>>(x);
    k_scatter<<<nb_e4, TB>>>(ei);
    k_l1node1<<<nb_n8, TB>>>(W1, b1);
    k_l2node23<<<1184, TB>>>(W2, b2, W3);   // 8 blocks/SM, grid-stride
    k_l3<<<nb_n8, TB>>>();
    k_pool<<<nb_nodes, TB>>>(batch);
    k_final<<<1, 256>>>(b3, out);
}